// round 5
// baseline (speedup 1.0000x reference)
#include <cuda_runtime.h>
#include <cstdint>

#define NB 512
#define NR 196
#define DV 1024
#define DH 512
#define DA 256
#define KC 32
#define TPB 256
#define AP 36                   // A smem pitch (floats) -> conflict-free frag/LDSM loads
#define A_STAGE (64 * AP)       // 2304 floats
#define B_STAGE (KC * DA)       // 8192 floats (fragment-major)
#define SMEM_FLOATS (2 * A_STAGE + 2 * B_STAGE + DA + DA + DA + 8)
#define SMEM_BYTES (SMEM_FLOATS * 4)

__device__ float g_Wv[DV * DA];     // tf32-rounded Wv, fragment-major [kc][ks][wn][m][lane][4]
__device__ float g_hproj[NB * DA];

// ---------------- helpers ----------------
static __device__ __forceinline__ uint32_t smem_u32(const void* p) {
    uint32_t a;
    asm("{ .reg .u64 t; cvta.to.shared.u64 t, %1; cvt.u32.u64 %0, t; }" : "=r"(a) : "l"(p));
    return a;
}
static __device__ __forceinline__ void cpa16(uint32_t dst, const void* src) {
    asm volatile("cp.async.cg.shared.global [%0], [%1], 16;" :: "r"(dst), "l"(src));
}
static __device__ __forceinline__ void cpa_commit() {
    asm volatile("cp.async.commit_group;" ::: "memory");
}
template <int N> static __device__ __forceinline__ void cpa_wait() {
    asm volatile("cp.async.wait_group %0;" :: "n"(N) : "memory");
}
static __device__ __forceinline__ void sts_zero16(uint32_t dst) {
    asm volatile("st.shared.v4.b32 [%0], {%1,%1,%1,%1};" :: "r"(dst), "r"(0) : "memory");
}
static __device__ __forceinline__ uint32_t to_tf32(float x) {
    uint32_t r;
    asm("cvt.rna.tf32.f32 %0, %1;" : "=r"(r) : "f"(x));
    return r;
}
static __device__ __forceinline__ void ldsm4(uint32_t* a, uint32_t addr) {
    asm volatile("ldmatrix.sync.aligned.m8n8.x4.shared.b16 {%0,%1,%2,%3}, [%4];"
                 : "=r"(a[0]), "=r"(a[1]), "=r"(a[2]), "=r"(a[3]) : "r"(addr));
}
static __device__ __forceinline__ void mma8(float* c, const uint32_t* a, uint32_t b0, uint32_t b1) {
    asm volatile(
        "mma.sync.aligned.m16n8k8.row.col.f32.tf32.tf32.f32 "
        "{%0,%1,%2,%3}, {%4,%5,%6,%7}, {%8,%9}, {%0,%1,%2,%3};"
        : "+f"(c[0]), "+f"(c[1]), "+f"(c[2]), "+f"(c[3])
        : "r"(a[0]), "r"(a[1]), "r"(a[2]), "r"(a[3]), "r"(b0), "r"(b1));
}

// ---------------- setup: Wv permute (blocks 0..1023) + hproj (blocks 1024..1535) ----------------
// Wv frag-major dst idx = ((((kc*4+ks)*4+wn)*4+m)*32+lane)*4+j
// col = wn*64 + 16*m + 8*(j>>1) + (lane>>2);  k = kc*32 + ks*8 + (lane&3) + 4*(j&1)
__global__ __launch_bounds__(DA) void setup_kernel(
    const float* __restrict__ Wv,
    const float* __restrict__ hidden, const float* __restrict__ Wh,
    const float* __restrict__ bh)
{
    if (blockIdx.x < 1024) {
        const int idx = blockIdx.x * DA + threadIdx.x;
        const int j    = idx & 3;
        const int lane = (idx >> 2) & 31;
        const int m    = (idx >> 7) & 3;
        const int wn   = (idx >> 9) & 3;
        const int ks   = (idx >> 11) & 3;
        const int kc   = idx >> 13;
        const int col = wn * 64 + 16 * m + 8 * (j >> 1) + (lane >> 2);
        const int k   = kc * 32 + ks * 8 + (lane & 3) + 4 * (j & 1);
        g_Wv[idx] = __uint_as_float(to_tf32(Wv[k * DA + col]));
    } else {
        const int b = blockIdx.x - 1024, a = threadIdx.x;
        const float* h = hidden + b * DH;
        const float* w = Wh + a;
        float acc = bh[a];
#pragma unroll 8
        for (int k = 0; k < DH; k++) acc = fmaf(h[k], w[k * DA], acc);
        g_hproj[b * DA + a] = acc;
    }
}

// ---------------- staging (double-buffered cp.async) ----------------
static __device__ __forceinline__ void stage_chunk(int idx, uint32_t sA, uint32_t sB,
                                                   const float* __restrict__ vb, int t) {
    const int mc = idx >> 5, kc = idx & 31, buf = idx & 1;
    const int k0 = kc * KC;
    const uint32_t aB = sA + buf * (A_STAGE * 4);
    const uint32_t bB = sB + buf * (B_STAGE * 4);
#pragma unroll
    for (int i = 0; i < 2; i++) {                 // A: 64 rows x 8 segs of 16B
        int s = t + i * TPB;
        int row = s >> 3, seg = s & 7;
        int gr = mc * 64 + row;
        uint32_t dst = aB + row * (AP * 4) + seg * 16;
        if (gr < NR) cpa16(dst, vb + (size_t)gr * DV + k0 + seg * 4);
        else         sts_zero16(dst);
    }
    const float* bsrc = g_Wv + (size_t)kc * B_STAGE;
#pragma unroll
    for (int i = 0; i < 8; i++) {                 // B: flat 32KB fragment-major copy
        int s = t + i * TPB;
        cpa16(bB + s * 16, bsrc + s * 4);
    }
}

// ---------------- fused kernel: one CTA per batch, 1 CTA/SM (full reg budget) ----------------
__global__ __launch_bounds__(TPB, 1) void fused_kernel(
    const float* __restrict__ visual,
    const float* __restrict__ bv,
    const float* __restrict__ Wa,
    float* __restrict__ out)
{
    extern __shared__ float smem[];
    float* As  = smem;
    float* Bs  = smem + 2 * A_STAGE;
    float* hpS = Bs + 2 * B_STAGE;
    float* waS = hpS + DA;
    float* scS = waS + DA;
    float* red = scS + DA;

    const int b = blockIdx.x, t = threadIdx.x;
    const int wid = t >> 5, lane = t & 31, g = lane >> 2, tg = lane & 3;
    const int warp_m = wid >> 2, warp_n = wid & 3;    // 2 x 4 warp grid: 64 rows x 256 cols
    const float* vb = visual + (size_t)b * NR * DV;

    hpS[t] = g_hproj[b * DA + t] + bv[t];
    waS[t] = Wa[t];
    scS[t] = 0.0f;

    const uint32_t sA = smem_u32(As), sB = smem_u32(Bs);
    // ldmatrix per-lane source: row (lane&15), fp32-col offset ((lane>>2)&4)
    const uint32_t lmLane = (uint32_t)((lane & 15) * (AP * 4) + ((lane >> 2) & 4) * 4);

    stage_chunk(0, sA, sB, vb, t);
    cpa_commit();

    float acc[2][8][4];
#pragma unroll
    for (int mf = 0; mf < 2; mf++)
#pragma unroll
        for (int nf = 0; nf < 8; nf++)
#pragma unroll
            for (int i = 0; i < 4; i++) acc[mf][nf][i] = 0.0f;

    for (int mc = 0; mc < 4; mc++) {
        // tail chunk (rows 192..255): only rows 192..207 matter
        const int nmf = (mc == 3) ? ((warp_m == 0) ? 1 : 0) : 2;

        for (int kc = 0; kc < 32; kc++) {
            const int idx = mc * 32 + kc;
            if (idx) __syncthreads();                  // WAR: buffer being restaged is free
            if (idx + 1 < 128) {
                stage_chunk(idx + 1, sA, sB, vb, t);
                cpa_commit();
                cpa_wait<1>();                         // chunk idx landed (this thread)
            } else {
                cpa_wait<0>();
            }
            __syncthreads();                           // all threads' data landed

            const int buf = idx & 1;
            const uint32_t aW = sA + (uint32_t)buf * (A_STAGE * 4)
                              + (uint32_t)(warp_m * 32) * (AP * 4) + lmLane;
            const float4* Bf = (const float4*)(Bs + buf * B_STAGE) + (warp_n * 4) * 32 + lane;
#pragma unroll
            for (int ks = 0; ks < 4; ks++) {
                uint32_t a[2][4];
#pragma unroll
                for (int mf = 0; mf < 2; mf++)
                    if (mf < nmf) ldsm4(a[mf], aW + mf * (16 * AP * 4) + ks * 32);

                const float4* Bk = Bf + (ks * 16) * 32;    // [ks][wn] block, this lane
#pragma unroll
                for (int m = 0; m < 4; m++) {
                    const float4 f = Bk[m * 32];
                    const uint32_t b00 = __float_as_uint(f.x), b01 = __float_as_uint(f.y);
                    const uint32_t b10 = __float_as_uint(f.z), b11 = __float_as_uint(f.w);
#pragma unroll
                    for (int mf = 0; mf < 2; mf++) {
                        if (mf < nmf) {
                            mma8(acc[mf][2 * m],     a[mf], b00, b01);
                            mma8(acc[mf][2 * m + 1], a[mf], b10, b11);
                        }
                    }
                }
            }
        }

        // ---- per-M-chunk score epilogue: relu(c+hp)*wa, reduce over 256 cols ----
        {
            float pA[2] = {0.0f, 0.0f}, pB[2] = {0.0f, 0.0f};
#pragma unroll
            for (int nf = 0; nf < 8; nf++) {
                const int col = warp_n * 64 + nf * 8 + 2 * tg;
                const float hp0 = hpS[col], hp1 = hpS[col + 1];
                const float wa0 = waS[col], wa1 = waS[col + 1];
#pragma unroll
                for (int mf = 0; mf < 2; mf++) {
                    if (mf < nmf) {
                        pA[mf] += fmaxf(acc[mf][nf][0] + hp0, 0.0f) * wa0
                                + fmaxf(acc[mf][nf][1] + hp1, 0.0f) * wa1;
                        pB[mf] += fmaxf(acc[mf][nf][2] + hp0, 0.0f) * wa0
                                + fmaxf(acc[mf][nf][3] + hp1, 0.0f) * wa1;
                        acc[mf][nf][0] = acc[mf][nf][1] = 0.0f;
                        acc[mf][nf][2] = acc[mf][nf][3] = 0.0f;
                    }
                }
            }
#pragma unroll
            for (int mf = 0; mf < 2; mf++) {
                if (mf < nmf) {
                    pA[mf] += __shfl_xor_sync(0xffffffffu, pA[mf], 1);
                    pA[mf] += __shfl_xor_sync(0xffffffffu, pA[mf], 2);
                    pB[mf] += __shfl_xor_sync(0xffffffffu, pB[mf], 1);
                    pB[mf] += __shfl_xor_sync(0xffffffffu, pB[mf], 2);
                    if (tg == 0) {
                        const int r0 = mc * 64 + warp_m * 32 + mf * 16 + g;
                        atomicAdd(&scS[r0],     pA[mf]);
                        atomicAdd(&scS[r0 + 8], pB[mf]);
                    }
                }
            }
        }
    }
    __syncthreads();

    // ---- softmax over 196 scores ----
    const float sval = (t < NR) ? scS[t] : -3.0e38f;
    float v = sval;
#pragma unroll
    for (int off = 16; off; off >>= 1) v = fmaxf(v, __shfl_xor_sync(0xffffffffu, v, off));
    if (lane == 0) red[wid] = v;
    __syncthreads();
    float m = red[0];
#pragma unroll
    for (int w = 1; w < 8; w++) m = fmaxf(m, red[w]);

    const float e = (t < NR) ? __expf(sval - m) : 0.0f;
    float se = e;
#pragma unroll
    for (int off = 16; off; off >>= 1) se += __shfl_xor_sync(0xffffffffu, se, off);
    __syncthreads();
    if (lane == 0) red[wid] = se;
    __syncthreads();
    float den = 0.0f;
#pragma unroll
    for (int w = 0; w < 8; w++) den += red[w];
    scS[t] = e * (1.0f / den);          // attention weights
    __syncthreads();

    // ---- att_output[b][:] = sum_r att[r] * visual[b][r][:] (coalesced float4) ----
    {
        const float4* vb4 = (const float4*)vb;
        float4 o = make_float4(0.f, 0.f, 0.f, 0.f);
#pragma unroll 4
        for (int r = 0; r < NR; r++) {
            const float w = scS[r];
            const float4 x = vb4[r * (DV / 4) + t];
            o.x = fmaf(w, x.x, o.x);
            o.y = fmaf(w, x.y, o.y);
            o.z = fmaf(w, x.z, o.z);
            o.w = fmaf(w, x.w, o.w);
        }
        ((float4*)out)[(size_t)b * (DV / 4) + t] = o;
    }
}

extern "C" void kernel_launch(void* const* d_in, const int* in_sizes, int n_in,
                              void* d_out, int out_size) {
    const float* visual = (const float*)d_in[0];
    const float* hidden = (const float*)d_in[1];
    const float* Wv     = (const float*)d_in[2];
    const float* bv     = (const float*)d_in[3];
    const float* Wh     = (const float*)d_in[4];
    const float* bh     = (const float*)d_in[5];
    const float* Wa     = (const float*)d_in[6];
    // d_in[7] = ba: additive constant over regions -> softmax-invariant, intentionally unused
    float* out = (float*)d_out;
    (void)in_sizes; (void)n_in; (void)out_size;

    cudaFuncSetAttribute(fused_kernel, cudaFuncAttributeMaxDynamicSharedMemorySize, SMEM_BYTES);

    setup_kernel<<<1536, DA>>>(Wv, hidden, Wh, bh);
    fused_kernel<<<NB, TPB, SMEM_BYTES>>>(visual, bv, Wa, out);
}

// round 6
// speedup vs baseline: 1.3098x; 1.3098x over previous
#include <cuda_runtime.h>
#include <cstdint>

#define NB 512
#define NR 196
#define DV 1024
#define DH 512
#define DA 256
#define KC 32
#define TPB 256
#define AP 36                   // A smem pitch (floats) -> conflict-free frag loads
#define MT 128                  // M tile rows per chunk
#define A_STAGE (MT * AP)       // 4608 floats
#define B_STAGE (KC * DA)       // 8192 floats (fragment-major)
#define NST 3                   // pipeline stages
#define NCH 64                  // 2 M-chunks x 32 K-chunks
#define SMEM_FLOATS (NST * A_STAGE + NST * B_STAGE + DA + DA + DA + 8)
#define SMEM_BYTES (SMEM_FLOATS * 4)

__device__ float g_Wv[DV * DA];     // tf32-rounded Wv, fragment-major [kc][ks][wn][m][lane][4]
__device__ float g_hproj[NB * DA];

// ---------------- helpers ----------------
static __device__ __forceinline__ uint32_t smem_u32(const void* p) {
    uint32_t a;
    asm("{ .reg .u64 t; cvta.to.shared.u64 t, %1; cvt.u32.u64 %0, t; }" : "=r"(a) : "l"(p));
    return a;
}
static __device__ __forceinline__ void cpa16(uint32_t dst, const void* src) {
    asm volatile("cp.async.cg.shared.global [%0], [%1], 16;" :: "r"(dst), "l"(src));
}
static __device__ __forceinline__ void cpa_commit() {
    asm volatile("cp.async.commit_group;" ::: "memory");
}
template <int N> static __device__ __forceinline__ void cpa_wait() {
    asm volatile("cp.async.wait_group %0;" :: "n"(N) : "memory");
}
static __device__ __forceinline__ void sts_zero16(uint32_t dst) {
    asm volatile("st.shared.v4.b32 [%0], {%1,%1,%1,%1};" :: "r"(dst), "r"(0) : "memory");
}
static __device__ __forceinline__ uint32_t to_tf32(float x) {
    uint32_t r;
    asm("cvt.rna.tf32.f32 %0, %1;" : "=r"(r) : "f"(x));
    return r;
}
static __device__ __forceinline__ void mma8(float* c, const uint32_t* a, uint32_t b0, uint32_t b1) {
    asm volatile(
        "mma.sync.aligned.m16n8k8.row.col.f32.tf32.tf32.f32 "
        "{%0,%1,%2,%3}, {%4,%5,%6,%7}, {%8,%9}, {%0,%1,%2,%3};"
        : "+f"(c[0]), "+f"(c[1]), "+f"(c[2]), "+f"(c[3])
        : "r"(a[0]), "r"(a[1]), "r"(a[2]), "r"(a[3]), "r"(b0), "r"(b1));
}

// ---------------- setup: Wv permute (blocks 0..1023) + hproj (blocks 1024..1535) ----------------
__global__ __launch_bounds__(DA) void setup_kernel(
    const float* __restrict__ Wv,
    const float* __restrict__ hidden, const float* __restrict__ Wh,
    const float* __restrict__ bh)
{
    if (blockIdx.x < 1024) {
        const int idx = blockIdx.x * DA + threadIdx.x;
        const int j    = idx & 3;
        const int lane = (idx >> 2) & 31;
        const int m    = (idx >> 7) & 3;
        const int wn   = (idx >> 9) & 3;
        const int ks   = (idx >> 11) & 3;
        const int kc   = idx >> 13;
        const int col = wn * 64 + 16 * m + 8 * (j >> 1) + (lane >> 2);
        const int k   = kc * 32 + ks * 8 + (lane & 3) + 4 * (j & 1);
        g_Wv[idx] = __uint_as_float(to_tf32(Wv[k * DA + col]));
    } else {
        const int b = blockIdx.x - 1024, a = threadIdx.x;
        const float* h = hidden + b * DH;
        const float* w = Wh + a;
        float acc = bh[a];
#pragma unroll 8
        for (int k = 0; k < DH; k++) acc = fmaf(h[k], w[k * DA], acc);
        g_hproj[b * DA + a] = acc;
    }
}

// ---------------- staging: chunk idx -> stage buffer sbuf ----------------
static __device__ __forceinline__ void stage_chunk(int idx, int sbuf, uint32_t sA, uint32_t sB,
                                                   const float* __restrict__ vb, int t) {
    const int mc = idx >> 5, kc = idx & 31;
    const int k0 = kc * KC;
    const uint32_t aB = sA + (uint32_t)sbuf * (A_STAGE * 4);
    const uint32_t bB = sB + (uint32_t)sbuf * (B_STAGE * 4);
#pragma unroll
    for (int i = 0; i < 4; i++) {                 // A: 128 rows x 8 segs of 16B
        int s = t + i * TPB;
        int row = s >> 3, seg = s & 7;
        int gr = mc * MT + row;
        uint32_t dst = aB + row * (AP * 4) + seg * 16;
        if (gr < NR) cpa16(dst, vb + (size_t)gr * DV + k0 + seg * 4);
        else         sts_zero16(dst);
    }
    const float* bsrc = g_Wv + (size_t)kc * B_STAGE;
#pragma unroll
    for (int i = 0; i < 8; i++) {                 // B: flat 32KB fragment-major copy
        int s = t + i * TPB;
        cpa16(bB + s * 16, bsrc + s * 4);
    }
}

// ---------------- fused kernel: one CTA per batch, M-tile 128, 3-stage 1-sync ----------------
__global__ __launch_bounds__(TPB, 1) void fused_kernel(
    const float* __restrict__ visual,
    const float* __restrict__ bv,
    const float* __restrict__ Wa,
    float* __restrict__ out)
{
    extern __shared__ float smem[];
    float* As  = smem;
    float* Bs  = smem + NST * A_STAGE;
    float* hpS = Bs + NST * B_STAGE;
    float* waS = hpS + DA;
    float* scS = waS + DA;
    float* red = scS + DA;

    const int b = blockIdx.x, t = threadIdx.x;
    const int wid = t >> 5, lane = t & 31, g = lane >> 2, tg = lane & 3;
    const int warp_m = wid >> 2, warp_n = wid & 3;    // 2x4 warps: 128 rows x 256 cols
    const float* vb = visual + (size_t)b * NR * DV;

    hpS[t] = g_hproj[b * DA + t] + bv[t];
    waS[t] = Wa[t];
    scS[t] = 0.0f;

    const uint32_t sA = smem_u32(As), sB = smem_u32(Bs);

    // prologue: stages for chunks 0 and 1
    stage_chunk(0, 0, sA, sB, vb, t); cpa_commit();
    stage_chunk(1, 1, sA, sB, vb, t); cpa_commit();

    float acc[4][8][4];
#pragma unroll
    for (int mf = 0; mf < 4; mf++)
#pragma unroll
        for (int nf = 0; nf < 8; nf++)
#pragma unroll
            for (int i = 0; i < 4; i++) acc[mf][nf][i] = 0.0f;

    int buf = 0;            // compute buffer for current chunk
    for (int mc = 0; mc < 2; mc++) {
        // mc=1 covers rows 128..255; valid to 195 -> warp_m0 all 4 mf, warp_m1 only mf0 (192..207)
        const int nmf = (mc == 0) ? 4 : ((warp_m == 0) ? 4 : 1);

        for (int kc = 0; kc < 32; kc++) {
            const int idx = mc * 32 + kc;
            if (idx == NCH - 1) cpa_wait<0>(); else cpa_wait<1>();   // data for chunk idx landed
            __syncthreads();                                          // single barrier per chunk
            if (idx + 2 < NCH) {
                int sbuf = buf == 0 ? 2 : buf - 1;                    // (idx+2)%3 == (buf+2)%3
                stage_chunk(idx + 2, sbuf, sA, sB, vb, t);
                cpa_commit();
            }

            const float*  A  = As + buf * A_STAGE + (warp_m * 64) * AP;
            const float4* Bf = (const float4*)(Bs + buf * B_STAGE) + (warp_n * 4) * 32 + lane;
#pragma unroll
            for (int ks = 0; ks < 4; ks++) {
                const int kk = ks * 8;
                uint32_t a[4][4];
#pragma unroll
                for (int mf = 0; mf < 4; mf++) {
                    if (mf < nmf) {
                        const float* ar = A + (mf * 16 + g) * AP + kk + tg;
                        a[mf][0] = __float_as_uint(ar[0]);
                        a[mf][1] = __float_as_uint(ar[8 * AP]);
                        a[mf][2] = __float_as_uint(ar[4]);
                        a[mf][3] = __float_as_uint(ar[8 * AP + 4]);
                    }
                }
                const float4* Bk = Bf + (ks * 16) * 32;
#pragma unroll
                for (int m = 0; m < 4; m++) {
                    const float4 f = Bk[m * 32];
                    const uint32_t b00 = __float_as_uint(f.x), b01 = __float_as_uint(f.y);
                    const uint32_t b10 = __float_as_uint(f.z), b11 = __float_as_uint(f.w);
#pragma unroll
                    for (int mf = 0; mf < 4; mf++) {
                        if (mf < nmf) {
                            mma8(acc[mf][2 * m],     a[mf], b00, b01);
                            mma8(acc[mf][2 * m + 1], a[mf], b10, b11);
                        }
                    }
                }
            }
            buf = (buf == 2) ? 0 : buf + 1;
        }

        // ---- per-M-chunk score epilogue: relu(c+hp)*wa, reduce over 256 cols ----
        {
            float pA[4] = {0, 0, 0, 0}, pB[4] = {0, 0, 0, 0};
#pragma unroll
            for (int nf = 0; nf < 8; nf++) {
                const int col = warp_n * 64 + nf * 8 + 2 * tg;
                const float hp0 = hpS[col], hp1 = hpS[col + 1];
                const float wa0 = waS[col], wa1 = waS[col + 1];
#pragma unroll
                for (int mf = 0; mf < 4; mf++) {
                    if (mf < nmf) {
                        pA[mf] += fmaxf(acc[mf][nf][0] + hp0, 0.0f) * wa0
                                + fmaxf(acc[mf][nf][1] + hp1, 0.0f) * wa1;
                        pB[mf] += fmaxf(acc[mf][nf][2] + hp0, 0.0f) * wa0
                                + fmaxf(acc[mf][nf][3] + hp1, 0.0f) * wa1;
                        acc[mf][nf][0] = acc[mf][nf][1] = 0.0f;
                        acc[mf][nf][2] = acc[mf][nf][3] = 0.0f;
                    }
                }
            }
#pragma unroll
            for (int mf = 0; mf < 4; mf++) {
                if (mf < nmf) {
                    pA[mf] += __shfl_xor_sync(0xffffffffu, pA[mf], 1);
                    pA[mf] += __shfl_xor_sync(0xffffffffu, pA[mf], 2);
                    pB[mf] += __shfl_xor_sync(0xffffffffu, pB[mf], 1);
                    pB[mf] += __shfl_xor_sync(0xffffffffu, pB[mf], 2);
                    if (tg == 0) {
                        const int r0 = mc * MT + warp_m * 64 + mf * 16 + g;
                        atomicAdd(&scS[r0],     pA[mf]);
                        atomicAdd(&scS[r0 + 8], pB[mf]);
                    }
                }
            }
        }
    }
    __syncthreads();

    // ---- softmax over 196 scores ----
    const float sval = (t < NR) ? scS[t] : -3.0e38f;
    float v = sval;
#pragma unroll
    for (int off = 16; off; off >>= 1) v = fmaxf(v, __shfl_xor_sync(0xffffffffu, v, off));
    if (lane == 0) red[wid] = v;
    __syncthreads();
    float m = red[0];
#pragma unroll
    for (int w = 1; w < 8; w++) m = fmaxf(m, red[w]);

    const float e = (t < NR) ? __expf(sval - m) : 0.0f;
    float se = e;
#pragma unroll
    for (int off = 16; off; off >>= 1) se += __shfl_xor_sync(0xffffffffu, se, off);
    __syncthreads();
    if (lane == 0) red[wid] = se;
    __syncthreads();
    float den = 0.0f;
#pragma unroll
    for (int w = 0; w < 8; w++) den += red[w];
    scS[t] = e * (1.0f / den);          // attention weights
    __syncthreads();

    // ---- att_output[b][:] = sum_r att[r] * visual[b][r][:] (coalesced float4) ----
    {
        const float4* vb4 = (const float4*)vb;
        float4 o = make_float4(0.f, 0.f, 0.f, 0.f);
#pragma unroll 4
        for (int r = 0; r < NR; r++) {
            const float w = scS[r];
            const float4 x = vb4[r * (DV / 4) + t];
            o.x = fmaf(w, x.x, o.x);
            o.y = fmaf(w, x.y, o.y);
            o.z = fmaf(w, x.z, o.z);
            o.w = fmaf(w, x.w, o.w);
        }
        ((float4*)out)[(size_t)b * (DV / 4) + t] = o;
    }
}

extern "C" void kernel_launch(void* const* d_in, const int* in_sizes, int n_in,
                              void* d_out, int out_size) {
    const float* visual = (const float*)d_in[0];
    const float* hidden = (const float*)d_in[1];
    const float* Wv     = (const float*)d_in[2];
    const float* bv     = (const float*)d_in[3];
    const float* Wh     = (const float*)d_in[4];
    const float* bh     = (const float*)d_in[5];
    const float* Wa     = (const float*)d_in[6];
    // d_in[7] = ba: additive constant over regions -> softmax-invariant, intentionally unused
    float* out = (float*)d_out;
    (void)in_sizes; (void)n_in; (void)out_size;

    cudaFuncSetAttribute(fused_kernel, cudaFuncAttributeMaxDynamicSharedMemorySize, SMEM_BYTES);

    setup_kernel<<<1536, DA>>>(Wv, hidden, Wh, bh);
    fused_kernel<<<NB, TPB, SMEM_BYTES>>>(visual, bv, Wa, out);
}

// round 7
// speedup vs baseline: 1.4829x; 1.1321x over previous
#include <cuda_runtime.h>
#include <cstdint>

#define NB 512
#define NR 196
#define DV 1024
#define DH 512
#define DA 256
#define KC 32
#define TPB 256
#define AP 36                   // A smem pitch (floats) -> conflict-free frag loads
#define MT 64                   // M tile rows per chunk
#define A_STAGE (MT * AP)       // 2304 floats
#define B_STAGE (KC * DA)       // 8192 floats (fragment-major)
#define NCH 128                 // 4 M-chunks x 32 K-chunks
#define SMEM_FLOATS (2 * A_STAGE + 2 * B_STAGE + DA + DA + DA + 64 + 8)
#define SMEM_BYTES (SMEM_FLOATS * 4)

__device__ float g_Wv[DV * DA];     // tf32-rounded Wv, fragment-major [kc][ks][wn][m][lane][4]
__device__ float g_hproj[NB * DA];

// ---------------- helpers ----------------
static __device__ __forceinline__ uint32_t smem_u32(const void* p) {
    uint32_t a;
    asm("{ .reg .u64 t; cvta.to.shared.u64 t, %1; cvt.u32.u64 %0, t; }" : "=r"(a) : "l"(p));
    return a;
}
static __device__ __forceinline__ void cpa16(uint32_t dst, const void* src) {
    asm volatile("cp.async.cg.shared.global [%0], [%1], 16;" :: "r"(dst), "l"(src));
}
static __device__ __forceinline__ void cpa_commit() {
    asm volatile("cp.async.commit_group;" ::: "memory");
}
template <int N> static __device__ __forceinline__ void cpa_wait() {
    asm volatile("cp.async.wait_group %0;" :: "n"(N) : "memory");
}
static __device__ __forceinline__ void sts_zero16(uint32_t dst) {
    asm volatile("st.shared.v4.b32 [%0], {%1,%1,%1,%1};" :: "r"(dst), "r"(0) : "memory");
}
static __device__ __forceinline__ uint32_t to_tf32(float x) {
    uint32_t r;
    asm("cvt.rna.tf32.f32 %0, %1;" : "=r"(r) : "f"(x));
    return r;
}
static __device__ __forceinline__ void mma8(float* c, const uint32_t* a, uint32_t b0, uint32_t b1) {
    asm volatile(
        "mma.sync.aligned.m16n8k8.row.col.f32.tf32.tf32.f32 "
        "{%0,%1,%2,%3}, {%4,%5,%6,%7}, {%8,%9}, {%0,%1,%2,%3};"
        : "+f"(c[0]), "+f"(c[1]), "+f"(c[2]), "+f"(c[3])
        : "r"(a[0]), "r"(a[1]), "r"(a[2]), "r"(a[3]), "r"(b0), "r"(b1));
}

// ---------------- setup: Wv permute (blocks 0..1023) + hproj (blocks 1024..1535) ----------------
__global__ __launch_bounds__(DA) void setup_kernel(
    const float* __restrict__ Wv,
    const float* __restrict__ hidden, const float* __restrict__ Wh,
    const float* __restrict__ bh)
{
    if (blockIdx.x < 1024) {
        const int idx = blockIdx.x * DA + threadIdx.x;
        const int j    = idx & 3;
        const int lane = (idx >> 2) & 31;
        const int m    = (idx >> 7) & 3;
        const int wn   = (idx >> 9) & 3;
        const int ks   = (idx >> 11) & 3;
        const int kc   = idx >> 13;
        const int col = wn * 64 + 16 * m + 8 * (j >> 1) + (lane >> 2);
        const int k   = kc * 32 + ks * 8 + (lane & 3) + 4 * (j & 1);
        g_Wv[idx] = __uint_as_float(to_tf32(Wv[k * DA + col]));
    } else {
        const int b = blockIdx.x - 1024, a = threadIdx.x;
        const float* h = hidden + b * DH;
        const float* w = Wh + a;
        float acc = bh[a];
#pragma unroll 8
        for (int k = 0; k < DH; k++) acc = fmaf(h[k], w[k * DA], acc);
        g_hproj[b * DA + a] = acc;
    }
}

// ---------------- staging (double-buffered cp.async) ----------------
static __device__ __forceinline__ void stage_chunk(int idx, uint32_t sA, uint32_t sB,
                                                   const float* __restrict__ vb, int t) {
    const int mc = idx >> 5, kc = idx & 31, buf = idx & 1;
    const int k0 = kc * KC;
    const uint32_t aB = sA + (uint32_t)buf * (A_STAGE * 4);
    const uint32_t bB = sB + (uint32_t)buf * (B_STAGE * 4);
#pragma unroll
    for (int i = 0; i < 2; i++) {                 // A: 64 rows x 8 segs of 16B
        int s = t + i * TPB;
        int row = s >> 3, seg = s & 7;
        int gr = mc * MT + row;
        uint32_t dst = aB + row * (AP * 4) + seg * 16;
        if (gr < NR) cpa16(dst, vb + (size_t)gr * DV + k0 + seg * 4);
        else         sts_zero16(dst);
    }
    const float* bsrc = g_Wv + (size_t)kc * B_STAGE;
#pragma unroll
    for (int i = 0; i < 8; i++) {                 // B: flat 32KB fragment-major copy
        int s = t + i * TPB;
        cpa16(bB + s * 16, bsrc + s * 4);
    }
}

// ---------------- fused: one CTA/batch, 2 CTAs/SM, online softmax per M-chunk ----------------
__global__ __launch_bounds__(TPB, 2) void fused_kernel(
    const float* __restrict__ visual,
    const float* __restrict__ bv,
    const float* __restrict__ Wa,
    float* __restrict__ out)
{
    extern __shared__ float smem[];
    float* As  = smem;
    float* Bs  = smem + 2 * A_STAGE;
    float* hpS = Bs + 2 * B_STAGE;
    float* waS = hpS + DA;
    float* scS = waS + DA;
    float* esS = scS + DA;          // 64 exp weights of current chunk
    float* misc = esS + 64;         // [0]=running max, [1]=den, [2]=rescale

    const int b = blockIdx.x, t = threadIdx.x;
    const int wid = t >> 5, lane = t & 31, g = lane >> 2, tg = lane & 3;
    const int warp_m = wid >> 2, warp_n = wid & 3;    // 2x4 warps: 64 rows x 256 cols
    const float* vb = visual + (size_t)b * NR * DV;
    const float4* vb4 = (const float4*)vb;

    hpS[t] = g_hproj[b * DA + t] + bv[t];
    waS[t] = Wa[t];
    scS[t] = 0.0f;
    if (t == 0) { misc[0] = -3.0e38f; misc[1] = 0.0f; misc[2] = 0.0f; }

    const uint32_t sA = smem_u32(As), sB = smem_u32(Bs);

    stage_chunk(0, sA, sB, vb, t);
    cpa_commit();

    float acc[2][8][4];
#pragma unroll
    for (int mf = 0; mf < 2; mf++)
#pragma unroll
        for (int nf = 0; nf < 8; nf++)
#pragma unroll
            for (int i = 0; i < 4; i++) acc[mf][nf][i] = 0.0f;

    float4 num = make_float4(0.f, 0.f, 0.f, 0.f);    // output dims 4t..4t+3

#pragma unroll 1
    for (int mc = 0; mc < 4; mc++) {
        // rows mc*64..mc*64+63; tail chunk: only rows 192..207 interesting
        const int nmf = (mc == 3) ? ((warp_m == 0) ? 1 : 0) : 2;

        for (int kc = 0; kc < 32; kc++) {
            const int idx = mc * 32 + kc;
            if (idx) __syncthreads();                  // WAR: restage target buffer drained
            if (idx + 1 < NCH) {
                stage_chunk(idx + 1, sA, sB, vb, t);
                cpa_commit();
                cpa_wait<1>();                         // chunk idx data landed (this thread)
            } else {
                cpa_wait<0>();
            }
            __syncthreads();                           // all threads' data landed

            const int buf = idx & 1;
            const float*  A  = As + buf * A_STAGE + (warp_m * 32) * AP;
            const float4* Bf = (const float4*)(Bs + buf * B_STAGE) + (warp_n * 4) * 32 + lane;
#pragma unroll
            for (int ks = 0; ks < 4; ks++) {
                const int kk = ks * 8;
                uint32_t a[2][4];
#pragma unroll
                for (int mf = 0; mf < 2; mf++) {
                    if (mf < nmf) {
                        const float* ar = A + (mf * 16 + g) * AP + kk + tg;
                        a[mf][0] = __float_as_uint(ar[0]);
                        a[mf][1] = __float_as_uint(ar[8 * AP]);
                        a[mf][2] = __float_as_uint(ar[4]);
                        a[mf][3] = __float_as_uint(ar[8 * AP + 4]);
                    }
                }
                const float4* Bk = Bf + (ks * 16) * 32;
#pragma unroll
                for (int m = 0; m < 4; m++) {
                    const float4 f = Bk[m * 32];
                    const uint32_t b00 = __float_as_uint(f.x), b01 = __float_as_uint(f.y);
                    const uint32_t b10 = __float_as_uint(f.z), b11 = __float_as_uint(f.w);
#pragma unroll
                    for (int mf = 0; mf < 2; mf++) {
                        if (mf < nmf) {
                            mma8(acc[mf][2 * m],     a[mf], b00, b01);
                            mma8(acc[mf][2 * m + 1], a[mf], b10, b11);
                        }
                    }
                }
            }
        }

        // ---- score epilogue: relu(c+hp)*wa, reduce over 256 cols -> scS ----
        {
            float pA[2] = {0.0f, 0.0f}, pB[2] = {0.0f, 0.0f};
#pragma unroll
            for (int nf = 0; nf < 8; nf++) {
                const int col = warp_n * 64 + nf * 8 + 2 * tg;
                const float hp0 = hpS[col], hp1 = hpS[col + 1];
                const float wa0 = waS[col], wa1 = waS[col + 1];
#pragma unroll
                for (int mf = 0; mf < 2; mf++) {
                    if (mf < nmf) {
                        pA[mf] += fmaxf(acc[mf][nf][0] + hp0, 0.0f) * wa0
                                + fmaxf(acc[mf][nf][1] + hp1, 0.0f) * wa1;
                        pB[mf] += fmaxf(acc[mf][nf][2] + hp0, 0.0f) * wa0
                                + fmaxf(acc[mf][nf][3] + hp1, 0.0f) * wa1;
                        acc[mf][nf][0] = acc[mf][nf][1] = 0.0f;
                        acc[mf][nf][2] = acc[mf][nf][3] = 0.0f;
                    }
                }
            }
#pragma unroll
            for (int mf = 0; mf < 2; mf++) {
                if (mf < nmf) {
                    pA[mf] += __shfl_xor_sync(0xffffffffu, pA[mf], 1);
                    pA[mf] += __shfl_xor_sync(0xffffffffu, pA[mf], 2);
                    pB[mf] += __shfl_xor_sync(0xffffffffu, pB[mf], 1);
                    pB[mf] += __shfl_xor_sync(0xffffffffu, pB[mf], 2);
                    if (tg == 0) {
                        const int r0 = mc * MT + warp_m * 32 + mf * 16 + g;
                        atomicAdd(&scS[r0],     pA[mf]);
                        atomicAdd(&scS[r0 + 8], pB[mf]);
                    }
                }
            }
        }
        __syncthreads();       // scores of this chunk final

        // ---- online softmax state update (warp 0): 64 scores, lanes own 2 rows ----
        if (wid == 0) {
            const int r0 = mc * MT;
            float s0 = (r0 + lane      < NR) ? scS[r0 + lane]      : -3.0e38f;
            float s1 = (r0 + 32 + lane < NR) ? scS[r0 + 32 + lane] : -3.0e38f;
            float mx = fmaxf(s0, s1);
#pragma unroll
            for (int off = 16; off; off >>= 1)
                mx = fmaxf(mx, __shfl_xor_sync(0xffffffffu, mx, off));
            const float Mold = misc[0];
            const float Mnew = fmaxf(Mold, mx);
            const float scl  = __expf(Mold - Mnew);   // first chunk: underflows to 0
            const float e0 = __expf(s0 - Mnew);
            const float e1 = __expf(s1 - Mnew);
            esS[lane]      = e0;
            esS[32 + lane] = e1;
            float se = e0 + e1;
#pragma unroll
            for (int off = 16; off; off >>= 1)
                se += __shfl_xor_sync(0xffffffffu, se, off);
            if (lane == 0) {
                misc[1] = misc[1] * scl + se;
                misc[0] = Mnew;
                misc[2] = scl;
            }
        }
        __syncthreads();

        // ---- numerator accumulation from L2-hot rows of this chunk ----
        {
            const float scl = misc[2];
            const int nrr = (mc < 3) ? MT : (NR - 3 * MT);   // 64 or 4
            float4 s = make_float4(0.f, 0.f, 0.f, 0.f);
            for (int rr = 0; rr < nrr; rr++) {
                const float e = esS[rr];
                const float4 x = vb4[(size_t)(mc * MT + rr) * (DV / 4) + t];
                s.x = fmaf(e, x.x, s.x);
                s.y = fmaf(e, x.y, s.y);
                s.z = fmaf(e, x.z, s.z);
                s.w = fmaf(e, x.w, s.w);
            }
            num.x = fmaf(num.x, scl, s.x);
            num.y = fmaf(num.y, scl, s.y);
            num.z = fmaf(num.z, scl, s.z);
            num.w = fmaf(num.w, scl, s.w);
        }
        __syncthreads();       // esS/misc stable before next chunk overwrites
    }

    // ---- final: out = num / den ----
    const float inv = 1.0f / misc[1];
    num.x *= inv; num.y *= inv; num.z *= inv; num.w *= inv;
    ((float4*)out)[(size_t)b * (DV / 4) + t] = num;
}

extern "C" void kernel_launch(void* const* d_in, const int* in_sizes, int n_in,
                              void* d_out, int out_size) {
    const float* visual = (const float*)d_in[0];
    const float* hidden = (const float*)d_in[1];
    const float* Wv     = (const float*)d_in[2];
    const float* bv     = (const float*)d_in[3];
    const float* Wh     = (const float*)d_in[4];
    const float* bh     = (const float*)d_in[5];
    const float* Wa     = (const float*)d_in[6];
    // d_in[7] = ba: additive constant over regions -> softmax-invariant, intentionally unused
    float* out = (float*)d_out;
    (void)in_sizes; (void)n_in; (void)out_size;

    cudaFuncSetAttribute(fused_kernel, cudaFuncAttributeMaxDynamicSharedMemorySize, SMEM_BYTES);

    setup_kernel<<<1536, DA>>>(Wv, hidden, Wh, bh);
    fused_kernel<<<NB, TPB, SMEM_BYTES>>>(visual, bv, Wa, out);
}